// round 1
// baseline (speedup 1.0000x reference)
#include <cuda_runtime.h>
#include <cuda_bf16.h>

// MaskCNN1: out[b,c,h,w] = (w < floor(W * percents[b])) ? x[b,c,h,w] : 0
// Shapes: x [16, 64, 80, 1024] fp32, percents [16] fp32.
// Pure streaming HBM-bound kernel. float4 vectorized; fully-masked vectors
// skip the global load entirely (write zeros only).

static constexpr int B = 16;
static constexpr int C = 64;
static constexpr int H = 80;
static constexpr int W = 1024;
static constexpr int W4 = W / 4;               // 256 float4 per row
static constexpr int PER_B4 = C * H * W4;      // float4 per batch = 1,310,720

__global__ __launch_bounds__(256)
void mask_cnn_kernel(const float4* __restrict__ x,
                     const float* __restrict__ percents,
                     float4* __restrict__ out) {
    // gridDim.y = B; gridDim.x covers PER_B4 / 256 blocks
    const int b   = blockIdx.y;
    const int idx = blockIdx.x * 256 + threadIdx.x;   // index within batch, in float4 units
    if (idx >= PER_B4) return;

    // length = int32(W * percents[b]) — truncation toward zero, matches JAX astype.
    const float p = __ldg(&percents[b]);
    const int len = (int)((float)W * p);

    const int w4  = idx & (W4 - 1);    // float4 column within the row
    const int pos = w4 << 2;           // first element position in W

    const long gidx = (long)b * PER_B4 + idx;

    if (pos + 3 < len) {
        // fully valid: straight copy
        out[gidx] = x[gidx];
    } else if (pos >= len) {
        // fully masked: write zeros, never read x
        out[gidx] = make_float4(0.f, 0.f, 0.f, 0.f);
    } else {
        // straddles the boundary (at most one float4 per row)
        float4 v = x[gidx];
        float4 r;
        r.x = (pos + 0 < len) ? v.x : 0.f;
        r.y = (pos + 1 < len) ? v.y : 0.f;
        r.z = (pos + 2 < len) ? v.z : 0.f;
        r.w = (pos + 3 < len) ? v.w : 0.f;
        out[gidx] = r;
    }
}

extern "C" void kernel_launch(void* const* d_in, const int* in_sizes, int n_in,
                              void* d_out, int out_size) {
    const float4* x        = (const float4*)d_in[0];
    const float*  percents = (const float*)d_in[1];
    float4*       out      = (float4*)d_out;

    dim3 grid(PER_B4 / 256, B, 1);   // 5120 x 16 blocks
    mask_cnn_kernel<<<grid, 256>>>(x, percents, out);
}

// round 2
// speedup vs baseline: 1.0048x; 1.0048x over previous
#include <cuda_runtime.h>
#include <cuda_bf16.h>

// MaskCNN1: out[b,c,h,w] = (w < floor(W * percents[b])) ? x[b,c,h,w] : 0
// x [16, 64, 80, 1024] fp32, percents [16] fp32. Streaming HBM-bound.
// R2: 4x unroll per thread with stride W4=256 so the W-column (and thus the
// mask predicate) is identical across the unroll -> one branch, 4 batched
// LDG.128 + 4 STG.128 per thread (MLP_p1=4). Fully-masked region never loads.

static constexpr int B = 16;
static constexpr int C = 64;
static constexpr int H = 80;
static constexpr int W = 1024;
static constexpr int W4 = W / 4;               // 256 float4 per row
static constexpr int PER_B4 = C * H * W4;      // 1,310,720 float4 per batch
static constexpr int UNROLL = 4;
static constexpr int BLOCK = 256;
static constexpr int PER_BLOCK = BLOCK * UNROLL;   // 1024 float4 (4 rows)

__global__ __launch_bounds__(BLOCK)
void mask_cnn_kernel(const float4* __restrict__ x,
                     const float* __restrict__ percents,
                     float4* __restrict__ out) {
    const int b   = blockIdx.y;
    const int tid = threadIdx.x;

    const float p = __ldg(&percents[b]);
    const int len = (int)((float)W * p);     // floor via int truncation (p >= 0)

    // Column is tid for every unrolled element (stride 256 == W4, block base
    // is a multiple of 256): pos identical across the unroll.
    const int pos = tid << 2;

    const long base = (long)b * PER_B4 + (long)blockIdx.x * PER_BLOCK + tid;

    if (pos + 3 < len) {
        // fully valid: 4 batched loads, then 4 stores
        float4 v0 = __ldcs(&x[base + 0 * 256]);
        float4 v1 = __ldcs(&x[base + 1 * 256]);
        float4 v2 = __ldcs(&x[base + 2 * 256]);
        float4 v3 = __ldcs(&x[base + 3 * 256]);
        __stcs(&out[base + 0 * 256], v0);
        __stcs(&out[base + 1 * 256], v1);
        __stcs(&out[base + 2 * 256], v2);
        __stcs(&out[base + 3 * 256], v3);
    } else if (pos >= len) {
        // fully masked: write zeros, never read x
        const float4 z = make_float4(0.f, 0.f, 0.f, 0.f);
        __stcs(&out[base + 0 * 256], z);
        __stcs(&out[base + 1 * 256], z);
        __stcs(&out[base + 2 * 256], z);
        __stcs(&out[base + 3 * 256], z);
    } else {
        // straddling float4 (one column per row): per-lane select
        float4 v0 = __ldcs(&x[base + 0 * 256]);
        float4 v1 = __ldcs(&x[base + 1 * 256]);
        float4 v2 = __ldcs(&x[base + 2 * 256]);
        float4 v3 = __ldcs(&x[base + 3 * 256]);
        const bool k0 = pos + 0 < len, k1 = pos + 1 < len,
                   k2 = pos + 2 < len, k3 = pos + 3 < len;
        v0.x = k0 ? v0.x : 0.f; v0.y = k1 ? v0.y : 0.f;
        v0.z = k2 ? v0.z : 0.f; v0.w = k3 ? v0.w : 0.f;
        v1.x = k0 ? v1.x : 0.f; v1.y = k1 ? v1.y : 0.f;
        v1.z = k2 ? v1.z : 0.f; v1.w = k3 ? v1.w : 0.f;
        v2.x = k0 ? v2.x : 0.f; v2.y = k1 ? v2.y : 0.f;
        v2.z = k2 ? v2.z : 0.f; v2.w = k3 ? v2.w : 0.f;
        v3.x = k0 ? v3.x : 0.f; v3.y = k1 ? v3.y : 0.f;
        v3.z = k2 ? v3.z : 0.f; v3.w = k3 ? v3.w : 0.f;
        __stcs(&out[base + 0 * 256], v0);
        __stcs(&out[base + 1 * 256], v1);
        __stcs(&out[base + 2 * 256], v2);
        __stcs(&out[base + 3 * 256], v3);
    }
}

extern "C" void kernel_launch(void* const* d_in, const int* in_sizes, int n_in,
                              void* d_out, int out_size) {
    const float4* x        = (const float4*)d_in[0];
    const float*  percents = (const float*)d_in[1];
    float4*       out      = (float4*)d_out;

    dim3 grid(PER_B4 / PER_BLOCK, B, 1);   // 1280 x 16 blocks
    mask_cnn_kernel<<<grid, BLOCK>>>(x, percents, out);
}

// round 3
// speedup vs baseline: 1.0056x; 1.0009x over previous
#include <cuda_runtime.h>
#include <cuda_bf16.h>

// MaskCNN1: out[b,c,h,w] = (w < floor(W * percents[b])) ? x[b,c,h,w] : 0
// x [16, 64, 80, 1024] fp32, percents [16] fp32. Streaming HBM-bound.
// R3: 8x unroll per thread, stride W4=256 so the W-column (and the mask
// predicate) is invariant across the unroll -> one branch per thread,
// 8 front-batched LDG.128 + 8 STG.128 (MLP_p1=8). Masked region never loads.

static constexpr int B = 16;
static constexpr int C = 64;
static constexpr int H = 80;
static constexpr int W = 1024;
static constexpr int W4 = W / 4;               // 256 float4 per row
static constexpr int PER_B4 = C * H * W4;      // 1,310,720 float4 per batch
static constexpr int UNROLL = 8;
static constexpr int BLOCK = 256;
static constexpr int PER_BLOCK = BLOCK * UNROLL;   // 2048 float4 (8 rows)

__global__ __launch_bounds__(BLOCK)
void mask_cnn_kernel(const float4* __restrict__ x,
                     const float* __restrict__ percents,
                     float4* __restrict__ out) {
    const int b   = blockIdx.y;
    const int tid = threadIdx.x;

    const float p = __ldg(&percents[b]);
    const int len = (int)((float)W * p);     // floor via int truncation (p >= 0)

    // Column == tid for every unrolled element (stride 256 == W4; block base
    // is a multiple of 256), so pos/predicate is unroll-invariant.
    const int pos = tid << 2;

    const long base = (long)b * PER_B4 + (long)blockIdx.x * PER_BLOCK + tid;

    if (pos + 3 < len) {
        // fully valid: 8 front-batched loads, then 8 stores
        float4 v[UNROLL];
        #pragma unroll
        for (int i = 0; i < UNROLL; i++) v[i] = __ldcs(&x[base + i * W4]);
        #pragma unroll
        for (int i = 0; i < UNROLL; i++) __stcs(&out[base + i * W4], v[i]);
    } else if (pos >= len) {
        // fully masked: write zeros, never read x
        const float4 z = make_float4(0.f, 0.f, 0.f, 0.f);
        #pragma unroll
        for (int i = 0; i < UNROLL; i++) __stcs(&out[base + i * W4], z);
    } else {
        // straddling float4 (one column): per-lane select, unroll-shared preds
        const bool k0 = pos + 0 < len, k1 = pos + 1 < len,
                   k2 = pos + 2 < len, k3 = pos + 3 < len;
        float4 v[UNROLL];
        #pragma unroll
        for (int i = 0; i < UNROLL; i++) v[i] = __ldcs(&x[base + i * W4]);
        #pragma unroll
        for (int i = 0; i < UNROLL; i++) {
            v[i].x = k0 ? v[i].x : 0.f;
            v[i].y = k1 ? v[i].y : 0.f;
            v[i].z = k2 ? v[i].z : 0.f;
            v[i].w = k3 ? v[i].w : 0.f;
        }
        #pragma unroll
        for (int i = 0; i < UNROLL; i++) __stcs(&out[base + i * W4], v[i]);
    }
}

extern "C" void kernel_launch(void* const* d_in, const int* in_sizes, int n_in,
                              void* d_out, int out_size) {
    const float4* x        = (const float4*)d_in[0];
    const float*  percents = (const float*)d_in[1];
    float4*       out      = (float4*)d_out;

    dim3 grid(PER_B4 / PER_BLOCK, B, 1);   // 640 x 16 blocks
    mask_cnn_kernel<<<grid, BLOCK>>>(x, percents, out);
}